// round 4
// baseline (speedup 1.0000x reference)
#include <cuda_runtime.h>

// ----------------------------------------------------------------------------
// ControlWhile: x = conv1x1(x, w_pre); while mean|x|<3: x = 10*conv(tanh(conv(x,
// w_shared)), w_loop); out = conv1x1(x, w_shared).
//
// Single persistent kernel, 1 block/SM (co-residency verified via occupancy
// query at launch), software grid barrier, data-dependent loop fully on-device
// (graph-capturable, no host sync). Each thread owns fixed pixel PAIRS across
// all phases; math runs on packed f32x2 (FFMA2) with weights in shared memory.
//
// R3 fix: batch-rollover in the grid-stride walk uses a while (stride >
// HWP when 148 blocks x 512 threads, so a single subtraction was WRONG in R2).
// ----------------------------------------------------------------------------

#define CIN    3
#define COUT   16
#define HW     147456           // 384*384
#define HWP    73728            // HW/2 (pairs per batch image)
#define NPIX   1179648          // 8*HW
#define NPAIR  589824           // NPIX/2
#define NTOT   18874368.0       // NPIX*COUT elements in v
#define THRESH (3.0 * NTOT)     // mean|v| < 3  <=>  sum|v| < 3*NTOT
#define MAX_IT 64
#define MAX_BLOCKS 1024
#define TPB    512

// Scratch tensor v (75.5 MB) — __device__ global (allocation rules forbid malloc)
__device__ float g_v[NPIX * COUT];
// Per-block |v| partial sums — fully overwritten every phase, so no stale state
// across graph replays; every block sums them in the same fixed order so the
// loop-termination decision is bit-identical everywhere.
__device__ double g_part[MAX_BLOCKS];
// Grid barrier state. count returns to 0 each barrier; gen is monotonic and
// compared by equality, so state is valid across unlimited graph replays.
__device__ unsigned int g_bar_count;
__device__ volatile unsigned int g_bar_gen;

// ---- packed f32x2 helpers (FFMA2 path: ptxas will not auto-fuse; PTX only) ----
__device__ __forceinline__ unsigned long long ffma2(unsigned long long a,
                                                    unsigned long long b,
                                                    unsigned long long c) {
    unsigned long long d;
    asm("fma.rn.f32x2 %0, %1, %2, %3;" : "=l"(d) : "l"(a), "l"(b), "l"(c));
    return d;
}
__device__ __forceinline__ unsigned long long fmul2(unsigned long long a,
                                                    unsigned long long b) {
    unsigned long long d;
    asm("mul.rn.f32x2 %0, %1, %2;" : "=l"(d) : "l"(a), "l"(b));
    return d;
}
__device__ __forceinline__ unsigned long long pack2(float lo, float hi) {
    unsigned long long d;
    asm("mov.b64 %0, {%1, %2};" : "=l"(d) : "f"(lo), "f"(hi));
    return d;
}
__device__ __forceinline__ void unpack2(unsigned long long v, float& lo, float& hi) {
    asm("mov.b64 {%0, %1}, %2;" : "=f"(lo), "=f"(hi) : "l"(v));
}

// tanh via exp: ~1e-7 rel err (deliberately NOT tanh.approx, whose ~6e-4 error
// could flip the data-dependent loop count). Clamp at 9: tanh(9) already rounds
// to 1.0f, so the clamp is exact in fp32.
__device__ __forceinline__ float tanhx(float x) {
    float xc = fminf(fmaxf(x, -9.0f), 9.0f);
    float t  = __expf(xc + xc);
    return __fdividef(t - 1.0f, t + 1.0f);
}

// Software grid barrier (all blocks co-resident by construction).
__device__ __forceinline__ void grid_bar() {
    __syncthreads();
    if (threadIdx.x == 0) {
        __threadfence();
        unsigned g = g_bar_gen;
        unsigned a = atomicAdd(&g_bar_count, 1u);
        if (a == gridDim.x - 1) {
            atomicExch(&g_bar_count, 0u);
            __threadfence();
            g_bar_gen = g + 1;
        } else {
            while (g_bar_gen == g) { __nanosleep(64); }
        }
    }
    __syncthreads();
}

// Block-reduce a float partial into g_part[blockIdx.x] (double).
__device__ __forceinline__ void store_block_partial(float part, double* s_wsum) {
    __syncthreads();  // protect s_wsum reuse across phases
    float v = part;
    #pragma unroll
    for (int o = 16; o > 0; o >>= 1) v += __shfl_xor_sync(0xffffffffu, v, o);
    if ((threadIdx.x & 31) == 0) s_wsum[threadIdx.x >> 5] = (double)v;
    __syncthreads();
    if (threadIdx.x == 0) {
        double s = 0.0;
        #pragma unroll
        for (int i = 0; i < TPB / 32; i++) s += s_wsum[i];
        g_part[blockIdx.x] = s;
    }
}

__global__ void __launch_bounds__(TPB, 1)
control_while_kernel(const float* __restrict__ x,
                     const float* __restrict__ wpre, const float* __restrict__ bpre,
                     const float* __restrict__ wloop, const float* __restrict__ bloop,
                     const float* __restrict__ wsh, const float* __restrict__ bsh,
                     float* __restrict__ out)
{
    __shared__ unsigned long long s_wpre[COUT * CIN];
    __shared__ unsigned long long s_wsh[COUT * COUT];
    __shared__ unsigned long long s_wl[COUT * COUT];
    __shared__ unsigned long long s_bpre[COUT], s_bsh[COUT], s_bl[COUT];
    __shared__ double s_wsum[TPB / 32];
    __shared__ double s_bcast;

    // Stage duplicated-packed weights in shared (LDS.64 broadcast feeds FFMA2)
    for (int i = threadIdx.x; i < COUT * COUT; i += TPB) {
        if (i < COUT * CIN) { float w = wpre[i]; s_wpre[i] = pack2(w, w); }
        float w0 = wsh[i];   s_wsh[i] = pack2(w0, w0);
        float w1 = wloop[i]; s_wl[i]  = pack2(w1, w1);
        if (i < COUT) {
            float b0 = bpre[i];  s_bpre[i] = pack2(b0, b0);
            float b1 = bsh[i];   s_bsh[i]  = pack2(b1, b1);
            float b2 = bloop[i]; s_bl[i]   = pack2(b2, b2);
        }
    }
    __syncthreads();

    const int gid    = blockIdx.x * TPB + threadIdx.x;
    const int stride = gridDim.x * TPB;

    // Decompose starting pair index once; advance b/r incrementally thereafter.
    // NOTE: stride may exceed HWP (148*512 = 75776 > 73728), so rollover must
    // be a while-loop, not a single conditional subtraction.
    const int b0i = gid / HWP;
    const int r0i = gid - b0i * HWP;

    // ---- phase 0: pre conv 3->16, accumulate sum|v| ----
    {
        float part = 0.f;
        int b = b0i, r = r0i;
        for (int q = gid; q < NPAIR; q += stride) {
            const float* xp = x   + (size_t)b * (CIN * HW)  + (r << 1);
            float*       vp = g_v + (size_t)b * (COUT * HW) + (r << 1);
            unsigned long long xin[CIN];
            #pragma unroll
            for (int c = 0; c < CIN; c++)
                xin[c] = *(const unsigned long long*)(xp + (size_t)c * HW);
            #pragma unroll
            for (int o = 0; o < COUT; o++) {
                unsigned long long a = s_bpre[o];
                #pragma unroll
                for (int c = 0; c < CIN; c++) a = ffma2(s_wpre[o * CIN + c], xin[c], a);
                *(unsigned long long*)(vp + (size_t)o * HW) = a;
                float lo, hi; unpack2(a, lo, hi);
                part += fabsf(lo) + fabsf(hi);
            }
            r += stride;
            while (r >= HWP) { r -= HWP; b++; }
        }
        store_block_partial(part, s_wsum);
    }
    grid_bar();

    const unsigned long long TEN2 = pack2(10.0f, 10.0f);

    // ---- data-dependent while loop, fully on-device ----
    for (int it = 0; it < MAX_IT; it++) {
        // decide: every block sums g_part in the same fixed order -> identical
        // double result -> identical break decision in all blocks.
        if (threadIdx.x == 0) {
            double s = 0.0;
            for (int i = 0; i < (int)gridDim.x; i++)
                s += ((volatile double*)g_part)[i];
            s_bcast = s;
        }
        __syncthreads();
        double tot = s_bcast;
        __syncthreads();
        if (!(tot < THRESH)) break;   // NaN-safe, same as jnp semantics

        float part = 0.f;
        int b = b0i, r = r0i;
        for (int q = gid; q < NPAIR; q += stride) {
            float* vp = g_v + (size_t)b * (COUT * HW) + (r << 1);
            unsigned long long vin[COUT], h[COUT];
            #pragma unroll
            for (int c = 0; c < COUT; c++)
                vin[c] = *(const unsigned long long*)(vp + (size_t)c * HW);
            // conv w_shared + tanh
            #pragma unroll
            for (int o = 0; o < COUT; o++) {
                unsigned long long a = s_bsh[o];
                #pragma unroll
                for (int c = 0; c < COUT; c++) a = ffma2(s_wsh[o * COUT + c], vin[c], a);
                float lo, hi; unpack2(a, lo, hi);
                h[o] = pack2(tanhx(lo), tanhx(hi));
            }
            // conv w_loop, *10, store in place, accumulate |.|
            #pragma unroll
            for (int o = 0; o < COUT; o++) {
                unsigned long long a = s_bl[o];
                #pragma unroll
                for (int c = 0; c < COUT; c++) a = ffma2(s_wl[o * COUT + c], h[c], a);
                a = fmul2(a, TEN2);
                *(unsigned long long*)(vp + (size_t)o * HW) = a;
                float lo, hi; unpack2(a, lo, hi);
                part += fabsf(lo) + fabsf(hi);
            }
            r += stride;
            while (r >= HWP) { r -= HWP; b++; }
        }
        store_block_partial(part, s_wsum);
        grid_bar();
    }

    // ---- final conv with w_shared -> out ----
    {
        int b = b0i, r = r0i;
        for (int q = gid; q < NPAIR; q += stride) {
            const float* vp = g_v + (size_t)b * (COUT * HW) + (r << 1);
            float*       op = out + (size_t)b * (COUT * HW) + (r << 1);
            unsigned long long vin[COUT];
            #pragma unroll
            for (int c = 0; c < COUT; c++)
                vin[c] = *(const unsigned long long*)(vp + (size_t)c * HW);
            #pragma unroll
            for (int o = 0; o < COUT; o++) {
                unsigned long long a = s_bsh[o];
                #pragma unroll
                for (int c = 0; c < COUT; c++) a = ffma2(s_wsh[o * COUT + c], vin[c], a);
                *(unsigned long long*)(op + (size_t)o * HW) = a;
            }
            r += stride;
            while (r >= HWP) { r -= HWP; b++; }
        }
    }
}

extern "C" void kernel_launch(void* const* d_in, const int* in_sizes, int n_in,
                              void* d_out, int out_size) {
    const float* x     = (const float*)d_in[0];
    const float* wpre  = (const float*)d_in[1];
    const float* bpre  = (const float*)d_in[2];
    const float* wloop = (const float*)d_in[3];
    const float* bloop = (const float*)d_in[4];
    const float* wsh   = (const float*)d_in[5];
    const float* bsh   = (const float*)d_in[6];
    (void)in_sizes; (void)n_in; (void)out_size;

    int dev = 0;
    cudaGetDevice(&dev);
    int sms = 0;
    cudaDeviceGetAttribute(&sms, cudaDevAttrMultiProcessorCount, dev);
    if (sms < 1) sms = 148;

    // Verify co-residency instead of assuming it: the software grid barrier is
    // deadlock-free iff gridDim <= sms * blocksPerSM. (Host-side query, not a
    // stream op — legal under graph capture.)
    int occ = 0;
    cudaOccupancyMaxActiveBlocksPerMultiprocessor(&occ, control_while_kernel,
                                                  TPB, 0);
    if (occ < 1) occ = 1;            // launch_bounds guarantees >=1 in practice
    long long maxb = (long long)sms * occ;
    int blocks = sms;                // 1/SM is the perf sweet spot
    if (blocks > maxb) blocks = (int)maxb;
    if (blocks > MAX_BLOCKS) blocks = MAX_BLOCKS;

    control_while_kernel<<<blocks, TPB>>>(x, wpre, bpre, wloop, bloop, wsh, bsh,
                                          (float*)d_out);
}